// round 15
// baseline (speedup 1.0000x reference)
#include <cuda_runtime.h>
#include <cuda_fp16.h>
#include <cstdint>

typedef unsigned long long ull;

__device__ __half g_xh[8*128*128*64];   // NHWC fp16 copy of x
__device__ uint4  g_bwi[8*128*9*128];   // {hw00|01, hw10|11, lin00|lin11<<16, 0}
__device__ float  g_w[4608];            // deform weights [k][g][cig][o8]

static __device__ __forceinline__ ull pk2(float lo, float hi){
    ull r; asm("mov.b64 %0, {%1, %2};" : "=l"(r) : "f"(lo), "f"(hi)); return r;
}
static __device__ __forceinline__ void unpk2(ull v, float& lo, float& hi){
    asm("mov.b64 {%0, %1}, %2;" : "=f"(lo), "=f"(hi) : "l"(v));
}
static __device__ __forceinline__ ull fma2(ull a, ull b, ull c){
    ull d; asm("fma.rn.f32x2 %0, %1, %2, %3;" : "=l"(d) : "l"(a), "l"(b), "l"(c)); return d;
}

// ---------------------------------------------------------------
// Kernel 1: offset conv 64->18 + bias + PReLU -> packed bilinear
// params (g_bwi), plus fp16 NHWC emit of x, plus (block 0) deform-
// weight transpose. 128 thr = 32x8 px tile, 2 px/thread, chunked
// channels, register prefetch, 1 bar/chunk. (Frozen core.)
// ---------------------------------------------------------------
__global__ __launch_bounds__(128) void k_offset(const float* __restrict__ x,
                                                const float* __restrict__ ow,
                                                const float* __restrict__ ob,
                                                const float* __restrict__ pa,
                                                const float* __restrict__ dw)
{
    __shared__ float tile[2][2720];            // [c(8)][r(10)][col(34)]
    __shared__ __align__(16) ull wch[2][720];  // [(c*9+k)][10 ull rows]

    int tid = threadIdx.x;
    int ty = tid >> 4, txq = (tid & 15) * 2;
    int x0 = blockIdx.x*32, y0 = blockIdx.y*8, b = blockIdx.z;

    if (blockIdx.x == 0 && blockIdx.y == 0 && blockIdx.z == 0){
        for (int i = tid; i < 4608; i += 128){
            float v = __ldg(&dw[i]);
            int o = i / 72, r = i - o*72;
            int cig = r / 9, k = r - cig*9;
            g_w[((k*8 + (o>>3))*8 + cig)*8 + (o&7)] = v;
        }
    }

    int t_off[22]; unsigned tmask = 0;
#pragma unroll
    for (int s = 0; s < 22; ++s){
        int i = tid + s*128;
        int c = i / 340, rr = i - c*340;
        int r = rr / 34, col = rr - r*34;
        int gy = y0 - 1 + r, gx = x0 - 1 + col;
        t_off[s] = c*16384 + gy*128 + gx;
        if (i < 2720 && (unsigned)gy < 128u && (unsigned)gx < 128u) tmask |= (1u << s);
    }
    int w_src[11], w_dst[11];
#pragma unroll
    for (int s = 0; s < 11; ++s){
        int i = tid + s*128;
        int oc = i / 72, r = i - oc*72;
        w_src[s] = (i < 1296) ? (oc*576 + r) : -1;
        w_dst[s] = r*20 + oc;
    }
    const float* xb = x + (size_t)b*(64*16384);

    ull acc0[9], acc1[9];
#pragma unroll
    for (int o9 = 0; o9 < 9; ++o9){
        ull b2 = pk2(__ldg(&ob[2*o9]), __ldg(&ob[2*o9+1]));
        acc0[o9] = b2; acc1[o9] = b2;
    }

#pragma unroll
    for (int s = 0; s < 11; ++s)
        if (w_src[s] >= 0)
            reinterpret_cast<float*>(wch[0])[w_dst[s]] = __ldg(&ow[w_src[s]]);
#pragma unroll
    for (int s = 0; s < 22; ++s){
        int i = tid + s*128;
        if (i < 2720)
            tile[0][i] = (tmask >> s & 1u) ? __ldg(&xb[t_off[s]]) : 0.f;
    }

    for (int ch = 0; ch < 8; ++ch){
        __syncthreads();
        int bf = ch & 1;
        float wv[11], tv[22];
        if (ch < 7){
            int c0n = (ch+1)*8;
#pragma unroll
            for (int s = 0; s < 11; ++s)
                wv[s] = (w_src[s] >= 0) ? __ldg(&ow[w_src[s] + c0n*9]) : 0.f;
#pragma unroll
            for (int s = 0; s < 22; ++s)
                tv[s] = (tmask >> s & 1u) ? __ldg(&xb[t_off[s] + c0n*16384]) : 0.f;
        }

        int c0 = ch*8;
#pragma unroll
        for (int e = 0; e < 2; ++e){
            int base = (ty+1)*34 + (txq+1+e);
            __half2 h[4];
            h[0] = __floats2half2_rn(tile[bf][0*340+base], tile[bf][1*340+base]);
            h[1] = __floats2half2_rn(tile[bf][2*340+base], tile[bf][3*340+base]);
            h[2] = __floats2half2_rn(tile[bf][4*340+base], tile[bf][5*340+base]);
            h[3] = __floats2half2_rn(tile[bf][6*340+base], tile[bf][7*340+base]);
            *reinterpret_cast<uint4*>(
                g_xh + ((size_t)(b*128 + y0+ty)*128 + x0+txq+e)*64 + c0)
                = *reinterpret_cast<const uint4*>(h);
        }

        for (int c = 0; c < 8; ++c){
#pragma unroll
            for (int ky = 0; ky < 3; ++ky){
                int rbase = c*340 + (ty+ky)*34 + txq;
                float2 va = *reinterpret_cast<const float2*>(&tile[bf][rbase]);
                float2 vb = *reinterpret_cast<const float2*>(&tile[bf][rbase+2]);
                float v[4] = {va.x, va.y, vb.x, vb.y};
#pragma unroll
                for (int kx = 0; kx < 3; ++kx){
                    const ulonglong2* wp2 = reinterpret_cast<const ulonglong2*>(
                        &wch[bf][(c*9 + ky*3 + kx)*10]);
                    ulonglong2 w01 = wp2[0], w23 = wp2[1], w45 = wp2[2], w67 = wp2[3];
                    ull w8 = wch[bf][(c*9 + ky*3 + kx)*10 + 8];
                    ull vv0 = pk2(v[kx],   v[kx]);
                    ull vv1 = pk2(v[kx+1], v[kx+1]);
                    acc0[0] = fma2(vv0, w01.x, acc0[0]); acc1[0] = fma2(vv1, w01.x, acc1[0]);
                    acc0[1] = fma2(vv0, w01.y, acc0[1]); acc1[1] = fma2(vv1, w01.y, acc1[1]);
                    acc0[2] = fma2(vv0, w23.x, acc0[2]); acc1[2] = fma2(vv1, w23.x, acc1[2]);
                    acc0[3] = fma2(vv0, w23.y, acc0[3]); acc1[3] = fma2(vv1, w23.y, acc1[3]);
                    acc0[4] = fma2(vv0, w45.x, acc0[4]); acc1[4] = fma2(vv1, w45.x, acc1[4]);
                    acc0[5] = fma2(vv0, w45.y, acc0[5]); acc1[5] = fma2(vv1, w45.y, acc1[5]);
                    acc0[6] = fma2(vv0, w67.x, acc0[6]); acc1[6] = fma2(vv1, w67.x, acc1[6]);
                    acc0[7] = fma2(vv0, w67.y, acc0[7]); acc1[7] = fma2(vv1, w67.y, acc1[7]);
                    acc0[8] = fma2(vv0, w8,    acc0[8]); acc1[8] = fma2(vv1, w8,    acc1[8]);
                }
            }
        }

        if (ch < 7){
            int nb = bf ^ 1;
#pragma unroll
            for (int s = 0; s < 11; ++s)
                if (w_src[s] >= 0)
                    reinterpret_cast<float*>(wch[nb])[w_dst[s]] = wv[s];
#pragma unroll
            for (int s = 0; s < 22; ++s){
                int i = tid + s*128;
                if (i < 2720) tile[nb][i] = tv[s];
            }
        }
    }

    // epilogue: PReLU + packed bilinear params (one STG.128 per px-tap)
    float a = __ldg(&pa[0]);
    int yy = y0 + ty;
#pragma unroll
    for (int e = 0; e < 2; ++e){
        int xx = x0 + txq + e;
#pragma unroll
        for (int k = 0; k < 9; ++k){
            float dy, dx;
            unpk2(e ? acc1[k] : acc0[k], dy, dx);
            dy = dy > 0.f ? dy : a*dy;
            dx = dx > 0.f ? dx : a*dx;
            float py  = (float)yy + (float)(k/3 - 1) + dy;
            float pxx = (float)xx + (float)(k%3 - 1) + dx;
            float y0f = floorf(py), x0f = floorf(pxx);
            float fy = py - y0f, fx = pxx - x0f;
            float vy0 = (y0f >=  0.f && y0f <= 127.f) ? 1.f : 0.f;
            float vy1 = (y0f >= -1.f && y0f <= 126.f) ? 1.f : 0.f;
            float vx0 = (x0f >=  0.f && x0f <= 127.f) ? 1.f : 0.f;
            float vx1 = (x0f >= -1.f && x0f <= 126.f) ? 1.f : 0.f;
            float w00 = (1.f-fy)*(1.f-fx)*vy0*vx0;
            float w01 = (1.f-fy)*fx*vy0*vx1;
            float w10 = fy*(1.f-fx)*vy1*vx0;
            float w11 = fy*fx*vy1*vx1;
            __half2 hxy = __floats2half2_rn(w00, w01);
            __half2 hzw = __floats2half2_rn(w10, w11);
            int y0i = (int)y0f, x0i = (int)x0f;
            int yc0 = min(max(y0i,   0), 127), yc1 = min(max(y0i+1, 0), 127);
            int xc0 = min(max(x0i,   0), 127), xc1 = min(max(x0i+1, 0), 127);
            unsigned lin00 = (unsigned)(yc0*128 + xc0);
            unsigned lin11 = (unsigned)(yc1*128 + xc1);
            uint4 o;
            o.x = *reinterpret_cast<unsigned*>(&hxy);
            o.y = *reinterpret_cast<unsigned*>(&hzw);
            o.z = lin00 | (lin11 << 16);
            o.w = 0u;
            g_bwi[((size_t)(b*128 + yy)*9 + k)*128 + xx] = o;
        }
    }
}

// ---------------------------------------------------------------
// Kernel 2: deformable grouped conv, software-pipelined gather.
// Block 256 thr = 64 px of a row. Per warp per iteration k:
//   issue corner LDGs for k+1 (params already in regs, 2-deep
//   prefetch) -> gemm(k) covers the L2 latency -> combine+STS k+1.
// half2 sample smem [c2][p] pitch 67 double-buffered + smem
// weights, 1 barrier/k. Gemm in fp32 f32x2.
// ---------------------------------------------------------------
__global__ __launch_bounds__(256) void k_deform(const float* __restrict__ db,
                                                float* __restrict__ out)
{
    __shared__ __align__(16) float s_w[4608];        // [k][g][cig][o8]
    __shared__ __align__(16) __half2 s_h[2][32*67];  // [c2][p] pitch 67

    int tid = threadIdx.x;
    int lane = tid & 31, wid = tid >> 5;
    int b = blockIdx.z, y = blockIdx.y, x0 = blockIdx.x*64;

    {
        const uint4* src = reinterpret_cast<const uint4*>(g_w);
        uint4* dst = reinterpret_cast<uint4*>(s_w);
        for (int i = tid; i < 1152; i += 256) dst[i] = src[i];
    }

    int q = lane & 15, ph = lane >> 4;    // phase-A identity
    int g = wid;                          // phase-B identity
    int p0 = lane, p1 = lane + 32;

    const uint2* xh = reinterpret_cast<const uint2*>(g_xh) + (size_t)b*(128*128*16);
    size_t rowp = ((size_t)(b*128 + y))*9;

    ull acc[8] = {0,0,0,0,0,0,0,0};       // [px(2)][opair(4)]

    uint4 P[4];         // params for the next gathered tap
    uint2 C[4][4];      // corner data in flight

    auto load_params = [&](int kk, uint4* Pp){
#pragma unroll
        for (int j = 0; j < 4; ++j){
            int pp = wid*8 + j*2 + ph;
            Pp[j] = __ldg(&g_bwi[(rowp + kk)*128 + x0 + pp]);
        }
    };
    auto issue_corners = [&](){
#pragma unroll
        for (int j = 0; j < 4; ++j){
            unsigned bi = P[j].z;
            int lin00 = bi & 0xFFFFu, lin11 = bi >> 16;
            int xc0 = lin00 & 127, xc1 = lin11 & 127;
            int y0b = lin00 - xc0, y1b = lin11 - xc1;
            C[j][0] = __ldg(&xh[(y0b + xc0)*16 + q]);
            C[j][1] = __ldg(&xh[(y0b + xc1)*16 + q]);
            C[j][2] = __ldg(&xh[(y1b + xc0)*16 + q]);
            C[j][3] = __ldg(&xh[(y1b + xc1)*16 + q]);
        }
    };
    auto combine_store = [&](__half2* buf){
#pragma unroll
        for (int j = 0; j < 4; ++j){
            int pp = wid*8 + j*2 + ph;
            __half2 wxy = *reinterpret_cast<__half2*>(&P[j].x);
            __half2 wzw = *reinterpret_cast<__half2*>(&P[j].y);
            __half2 h00 = __low2half2(wxy), h01 = __high2half2(wxy);
            __half2 h10 = __low2half2(wzw), h11 = __high2half2(wzw);
            __half2 sa = __hmul2(h00, *reinterpret_cast<__half2*>(&C[j][0].x));
            sa = __hfma2(h01, *reinterpret_cast<__half2*>(&C[j][1].x), sa);
            sa = __hfma2(h10, *reinterpret_cast<__half2*>(&C[j][2].x), sa);
            sa = __hfma2(h11, *reinterpret_cast<__half2*>(&C[j][3].x), sa);
            __half2 sb = __hmul2(h00, *reinterpret_cast<__half2*>(&C[j][0].y));
            sb = __hfma2(h01, *reinterpret_cast<__half2*>(&C[j][1].y), sb);
            sb = __hfma2(h10, *reinterpret_cast<__half2*>(&C[j][2].y), sb);
            sb = __hfma2(h11, *reinterpret_cast<__half2*>(&C[j][3].y), sb);
            buf[(2*q+0)*67 + pp] = sa;
            buf[(2*q+1)*67 + pp] = sb;
        }
    };

    // prologue: gather tap 0 directly, then preload params for tap 1
    load_params(0, P);
    issue_corners();
    combine_store(s_h[0]);
    load_params(1, P);

#pragma unroll 1
    for (int k = 0; k < 9; ++k){
        __syncthreads();      // weights + buf[k&1] ready; prior gemm reads done
        if (k < 8) issue_corners();        // corners for k+1, params in P
        uint4 Pn[4];
        if (k < 7) load_params(k+2, Pn);   // params two ahead

        // gemm(k) — independent of the in-flight gather loads
        {
            const __half2* cur = s_h[k & 1];
            float2 f0[4], f1[4];
#pragma unroll
            for (int i = 0; i < 4; ++i){
                f0[i] = __half22float2(cur[(g*4 + i)*67 + p0]);
                f1[i] = __half22float2(cur[(g*4 + i)*67 + p1]);
            }
            float sm0[8] = {f0[0].x,f0[0].y,f0[1].x,f0[1].y,f0[2].x,f0[2].y,f0[3].x,f0[3].y};
            float sm1[8] = {f1[0].x,f1[0].y,f1[1].x,f1[1].y,f1[2].x,f1[2].y,f1[3].x,f1[3].y};
            const ulonglong2* wk = reinterpret_cast<const ulonglong2*>(&s_w[(k*8 + g)*64]);
#pragma unroll
            for (int cig = 0; cig < 8; ++cig){
                ulonglong2 wab = wk[cig*2];
                ulonglong2 wcd = wk[cig*2+1];
                ull vv0 = pk2(sm0[cig], sm0[cig]);
                ull vv1 = pk2(sm1[cig], sm1[cig]);
                acc[0] = fma2(vv0, wab.x, acc[0]);
                acc[1] = fma2(vv0, wab.y, acc[1]);
                acc[2] = fma2(vv0, wcd.x, acc[2]);
                acc[3] = fma2(vv0, wcd.y, acc[3]);
                acc[4] = fma2(vv1, wab.x, acc[4]);
                acc[5] = fma2(vv1, wab.y, acc[5]);
                acc[6] = fma2(vv1, wcd.x, acc[6]);
                acc[7] = fma2(vv1, wcd.y, acc[7]);
            }
        }

        if (k < 8) combine_store(s_h[(k+1) & 1]);
        if (k < 7){ P[0]=Pn[0]; P[1]=Pn[1]; P[2]=Pn[2]; P[3]=Pn[3]; }
    }

    // epilogue: direct coalesced stores (lane = pixel -> consecutive x)
    float* orow = out + ((size_t)b*64*128 + y)*128 + x0;
#pragma unroll
    for (int op = 0; op < 4; ++op){
        int o0 = g*8 + 2*op;
        float b0 = __ldg(&db[o0]), b1 = __ldg(&db[o0+1]);
        float lo, hi;
        unpk2(acc[op], lo, hi);
        orow[(size_t)o0*16384 + p0]     = lo + b0;
        orow[(size_t)(o0+1)*16384 + p0] = hi + b1;
        unpk2(acc[4+op], lo, hi);
        orow[(size_t)o0*16384 + p1]     = lo + b0;
        orow[(size_t)(o0+1)*16384 + p1] = hi + b1;
    }
}

extern "C" void kernel_launch(void* const* d_in, const int* in_sizes, int n_in,
                              void* d_out, int out_size)
{
    const float* x  = (const float*)d_in[0];
    const float* ow = (const float*)d_in[1];
    const float* ob = (const float*)d_in[2];
    const float* pa = (const float*)d_in[3];
    const float* dw = (const float*)d_in[4];
    const float* db = (const float*)d_in[5];
    float* out = (float*)d_out;

    k_offset<<<dim3(4, 16, 8), 128>>>(x, ow, ob, pa, dw);
    k_deform<<<dim3(2, 128, 8), 256>>>(db, out);
}

// round 16
// speedup vs baseline: 1.0025x; 1.0025x over previous
#include <cuda_runtime.h>
#include <cuda_fp16.h>
#include <cstdint>

typedef unsigned long long ull;

__device__ __half g_xh[8*128*128*64];   // NHWC fp16 copy of x
__device__ uint4  g_bwi[8*128*9*128];   // {hw00|01, hw10|11, lin00|lin11<<16, 0}
__device__ float  g_w[4608];            // deform weights [k][g][cig][o8]

static __device__ __forceinline__ ull pk2(float lo, float hi){
    ull r; asm("mov.b64 %0, {%1, %2};" : "=l"(r) : "f"(lo), "f"(hi)); return r;
}
static __device__ __forceinline__ void unpk2(ull v, float& lo, float& hi){
    asm("mov.b64 {%0, %1}, %2;" : "=f"(lo), "=f"(hi) : "l"(v));
}
static __device__ __forceinline__ ull fma2(ull a, ull b, ull c){
    ull d; asm("fma.rn.f32x2 %0, %1, %2, %3;" : "=l"(d) : "l"(a), "l"(b), "l"(c)); return d;
}

// ---------------------------------------------------------------
// Kernel 1: offset conv 64->18 + bias + PReLU -> packed bilinear
// params (g_bwi), plus fp16 NHWC emit of x, plus (block 0) deform-
// weight transpose. 128 thr = 32x8 px tile, 2 px/thread, chunked
// channels, register prefetch, 1 bar/chunk. (Frozen core.)
// ---------------------------------------------------------------
__global__ __launch_bounds__(128) void k_offset(const float* __restrict__ x,
                                                const float* __restrict__ ow,
                                                const float* __restrict__ ob,
                                                const float* __restrict__ pa,
                                                const float* __restrict__ dw)
{
    __shared__ float tile[2][2720];            // [c(8)][r(10)][col(34)]
    __shared__ __align__(16) ull wch[2][720];  // [(c*9+k)][10 ull rows]

    int tid = threadIdx.x;
    int ty = tid >> 4, txq = (tid & 15) * 2;
    int x0 = blockIdx.x*32, y0 = blockIdx.y*8, b = blockIdx.z;

    if (blockIdx.x == 0 && blockIdx.y == 0 && blockIdx.z == 0){
        for (int i = tid; i < 4608; i += 128){
            float v = __ldg(&dw[i]);
            int o = i / 72, r = i - o*72;
            int cig = r / 9, k = r - cig*9;
            g_w[((k*8 + (o>>3))*8 + cig)*8 + (o&7)] = v;
        }
    }

    int t_off[22]; unsigned tmask = 0;
#pragma unroll
    for (int s = 0; s < 22; ++s){
        int i = tid + s*128;
        int c = i / 340, rr = i - c*340;
        int r = rr / 34, col = rr - r*34;
        int gy = y0 - 1 + r, gx = x0 - 1 + col;
        t_off[s] = c*16384 + gy*128 + gx;
        if (i < 2720 && (unsigned)gy < 128u && (unsigned)gx < 128u) tmask |= (1u << s);
    }
    int w_src[11], w_dst[11];
#pragma unroll
    for (int s = 0; s < 11; ++s){
        int i = tid + s*128;
        int oc = i / 72, r = i - oc*72;
        w_src[s] = (i < 1296) ? (oc*576 + r) : -1;
        w_dst[s] = r*20 + oc;
    }
    const float* xb = x + (size_t)b*(64*16384);

    ull acc0[9], acc1[9];
#pragma unroll
    for (int o9 = 0; o9 < 9; ++o9){
        ull b2 = pk2(__ldg(&ob[2*o9]), __ldg(&ob[2*o9+1]));
        acc0[o9] = b2; acc1[o9] = b2;
    }

#pragma unroll
    for (int s = 0; s < 11; ++s)
        if (w_src[s] >= 0)
            reinterpret_cast<float*>(wch[0])[w_dst[s]] = __ldg(&ow[w_src[s]]);
#pragma unroll
    for (int s = 0; s < 22; ++s){
        int i = tid + s*128;
        if (i < 2720)
            tile[0][i] = (tmask >> s & 1u) ? __ldg(&xb[t_off[s]]) : 0.f;
    }

    for (int ch = 0; ch < 8; ++ch){
        __syncthreads();
        int bf = ch & 1;
        float wv[11], tv[22];
        if (ch < 7){
            int c0n = (ch+1)*8;
#pragma unroll
            for (int s = 0; s < 11; ++s)
                wv[s] = (w_src[s] >= 0) ? __ldg(&ow[w_src[s] + c0n*9]) : 0.f;
#pragma unroll
            for (int s = 0; s < 22; ++s)
                tv[s] = (tmask >> s & 1u) ? __ldg(&xb[t_off[s] + c0n*16384]) : 0.f;
        }

        int c0 = ch*8;
#pragma unroll
        for (int e = 0; e < 2; ++e){
            int base = (ty+1)*34 + (txq+1+e);
            __half2 h[4];
            h[0] = __floats2half2_rn(tile[bf][0*340+base], tile[bf][1*340+base]);
            h[1] = __floats2half2_rn(tile[bf][2*340+base], tile[bf][3*340+base]);
            h[2] = __floats2half2_rn(tile[bf][4*340+base], tile[bf][5*340+base]);
            h[3] = __floats2half2_rn(tile[bf][6*340+base], tile[bf][7*340+base]);
            *reinterpret_cast<uint4*>(
                g_xh + ((size_t)(b*128 + y0+ty)*128 + x0+txq+e)*64 + c0)
                = *reinterpret_cast<const uint4*>(h);
        }

        for (int c = 0; c < 8; ++c){
#pragma unroll
            for (int ky = 0; ky < 3; ++ky){
                int rbase = c*340 + (ty+ky)*34 + txq;
                float2 va = *reinterpret_cast<const float2*>(&tile[bf][rbase]);
                float2 vb = *reinterpret_cast<const float2*>(&tile[bf][rbase+2]);
                float v[4] = {va.x, va.y, vb.x, vb.y};
#pragma unroll
                for (int kx = 0; kx < 3; ++kx){
                    const ulonglong2* wp2 = reinterpret_cast<const ulonglong2*>(
                        &wch[bf][(c*9 + ky*3 + kx)*10]);
                    ulonglong2 w01 = wp2[0], w23 = wp2[1], w45 = wp2[2], w67 = wp2[3];
                    ull w8 = wch[bf][(c*9 + ky*3 + kx)*10 + 8];
                    ull vv0 = pk2(v[kx],   v[kx]);
                    ull vv1 = pk2(v[kx+1], v[kx+1]);
                    acc0[0] = fma2(vv0, w01.x, acc0[0]); acc1[0] = fma2(vv1, w01.x, acc1[0]);
                    acc0[1] = fma2(vv0, w01.y, acc0[1]); acc1[1] = fma2(vv1, w01.y, acc1[1]);
                    acc0[2] = fma2(vv0, w23.x, acc0[2]); acc1[2] = fma2(vv1, w23.x, acc1[2]);
                    acc0[3] = fma2(vv0, w23.y, acc0[3]); acc1[3] = fma2(vv1, w23.y, acc1[3]);
                    acc0[4] = fma2(vv0, w45.x, acc0[4]); acc1[4] = fma2(vv1, w45.x, acc1[4]);
                    acc0[5] = fma2(vv0, w45.y, acc0[5]); acc1[5] = fma2(vv1, w45.y, acc1[5]);
                    acc0[6] = fma2(vv0, w67.x, acc0[6]); acc1[6] = fma2(vv1, w67.x, acc1[6]);
                    acc0[7] = fma2(vv0, w67.y, acc0[7]); acc1[7] = fma2(vv1, w67.y, acc1[7]);
                    acc0[8] = fma2(vv0, w8,    acc0[8]); acc1[8] = fma2(vv1, w8,    acc1[8]);
                }
            }
        }

        if (ch < 7){
            int nb = bf ^ 1;
#pragma unroll
            for (int s = 0; s < 11; ++s)
                if (w_src[s] >= 0)
                    reinterpret_cast<float*>(wch[nb])[w_dst[s]] = wv[s];
#pragma unroll
            for (int s = 0; s < 22; ++s){
                int i = tid + s*128;
                if (i < 2720) tile[nb][i] = tv[s];
            }
        }
    }

    // epilogue: PReLU + packed bilinear params (one STG.128 per px-tap)
    float a = __ldg(&pa[0]);
    int yy = y0 + ty;
#pragma unroll
    for (int e = 0; e < 2; ++e){
        int xx = x0 + txq + e;
#pragma unroll
        for (int k = 0; k < 9; ++k){
            float dy, dx;
            unpk2(e ? acc1[k] : acc0[k], dy, dx);
            dy = dy > 0.f ? dy : a*dy;
            dx = dx > 0.f ? dx : a*dx;
            float py  = (float)yy + (float)(k/3 - 1) + dy;
            float pxx = (float)xx + (float)(k%3 - 1) + dx;
            float y0f = floorf(py), x0f = floorf(pxx);
            float fy = py - y0f, fx = pxx - x0f;
            float vy0 = (y0f >=  0.f && y0f <= 127.f) ? 1.f : 0.f;
            float vy1 = (y0f >= -1.f && y0f <= 126.f) ? 1.f : 0.f;
            float vx0 = (x0f >=  0.f && x0f <= 127.f) ? 1.f : 0.f;
            float vx1 = (x0f >= -1.f && x0f <= 126.f) ? 1.f : 0.f;
            float w00 = (1.f-fy)*(1.f-fx)*vy0*vx0;
            float w01 = (1.f-fy)*fx*vy0*vx1;
            float w10 = fy*(1.f-fx)*vy1*vx0;
            float w11 = fy*fx*vy1*vx1;
            __half2 hxy = __floats2half2_rn(w00, w01);
            __half2 hzw = __floats2half2_rn(w10, w11);
            int y0i = (int)y0f, x0i = (int)x0f;
            int yc0 = min(max(y0i,   0), 127), yc1 = min(max(y0i+1, 0), 127);
            int xc0 = min(max(x0i,   0), 127), xc1 = min(max(x0i+1, 0), 127);
            unsigned lin00 = (unsigned)(yc0*128 + xc0);
            unsigned lin11 = (unsigned)(yc1*128 + xc1);
            uint4 o;
            o.x = *reinterpret_cast<unsigned*>(&hxy);
            o.y = *reinterpret_cast<unsigned*>(&hzw);
            o.z = lin00 | (lin11 << 16);
            o.w = 0u;
            g_bwi[((size_t)(b*128 + yy)*9 + k)*128 + xx] = o;
        }
    }
}

// ---------------------------------------------------------------
// Kernel 2: deformable grouped conv, software-pipelined gather.
// Block 256 thr = 64 px of a row. Per warp per iteration k:
//   issue corner LDGs for k+1 (params already in regs, 2-deep
//   prefetch) -> gemm(k) covers the L2 latency -> combine+STS k+1.
// half2 sample smem [c2][p] pitch 67 double-buffered + smem
// weights, 1 barrier/k. Gemm in fp32 f32x2.
// ---------------------------------------------------------------
__global__ __launch_bounds__(256) void k_deform(const float* __restrict__ db,
                                                float* __restrict__ out)
{
    __shared__ __align__(16) float s_w[4608];        // [k][g][cig][o8]
    __shared__ __align__(16) __half2 s_h[2][32*67];  // [c2][p] pitch 67

    int tid = threadIdx.x;
    int lane = tid & 31, wid = tid >> 5;
    int b = blockIdx.z, y = blockIdx.y, x0 = blockIdx.x*64;

    {
        const uint4* src = reinterpret_cast<const uint4*>(g_w);
        uint4* dst = reinterpret_cast<uint4*>(s_w);
        for (int i = tid; i < 1152; i += 256) dst[i] = src[i];
    }

    int q = lane & 15, ph = lane >> 4;    // phase-A identity
    int g = wid;                          // phase-B identity
    int p0 = lane, p1 = lane + 32;

    const uint2* xh = reinterpret_cast<const uint2*>(g_xh) + (size_t)b*(128*128*16);
    size_t rowp = ((size_t)(b*128 + y))*9;

    ull acc[8] = {0,0,0,0,0,0,0,0};       // [px(2)][opair(4)]

    uint4 P[4];         // params for the next gathered tap
    uint2 C[4][4];      // corner data in flight

    auto load_params = [&](int kk, uint4* Pp){
#pragma unroll
        for (int j = 0; j < 4; ++j){
            int pp = wid*8 + j*2 + ph;
            Pp[j] = __ldg(&g_bwi[(rowp + kk)*128 + x0 + pp]);
        }
    };
    auto issue_corners = [&](){
#pragma unroll
        for (int j = 0; j < 4; ++j){
            unsigned bi = P[j].z;
            int lin00 = bi & 0xFFFFu, lin11 = bi >> 16;
            int xc0 = lin00 & 127, xc1 = lin11 & 127;
            int y0b = lin00 - xc0, y1b = lin11 - xc1;
            C[j][0] = __ldg(&xh[(y0b + xc0)*16 + q]);
            C[j][1] = __ldg(&xh[(y0b + xc1)*16 + q]);
            C[j][2] = __ldg(&xh[(y1b + xc0)*16 + q]);
            C[j][3] = __ldg(&xh[(y1b + xc1)*16 + q]);
        }
    };
    auto combine_store = [&](__half2* buf){
#pragma unroll
        for (int j = 0; j < 4; ++j){
            int pp = wid*8 + j*2 + ph;
            __half2 wxy = *reinterpret_cast<__half2*>(&P[j].x);
            __half2 wzw = *reinterpret_cast<__half2*>(&P[j].y);
            __half2 h00 = __low2half2(wxy), h01 = __high2half2(wxy);
            __half2 h10 = __low2half2(wzw), h11 = __high2half2(wzw);
            __half2 sa = __hmul2(h00, *reinterpret_cast<__half2*>(&C[j][0].x));
            sa = __hfma2(h01, *reinterpret_cast<__half2*>(&C[j][1].x), sa);
            sa = __hfma2(h10, *reinterpret_cast<__half2*>(&C[j][2].x), sa);
            sa = __hfma2(h11, *reinterpret_cast<__half2*>(&C[j][3].x), sa);
            __half2 sb = __hmul2(h00, *reinterpret_cast<__half2*>(&C[j][0].y));
            sb = __hfma2(h01, *reinterpret_cast<__half2*>(&C[j][1].y), sb);
            sb = __hfma2(h10, *reinterpret_cast<__half2*>(&C[j][2].y), sb);
            sb = __hfma2(h11, *reinterpret_cast<__half2*>(&C[j][3].y), sb);
            buf[(2*q+0)*67 + pp] = sa;
            buf[(2*q+1)*67 + pp] = sb;
        }
    };

    // prologue: gather tap 0 directly, then preload params for tap 1
    load_params(0, P);
    issue_corners();
    combine_store(s_h[0]);
    load_params(1, P);

#pragma unroll 1
    for (int k = 0; k < 9; ++k){
        __syncthreads();      // weights + buf[k&1] ready; prior gemm reads done
        if (k < 8) issue_corners();        // corners for k+1, params in P
        uint4 Pn[4];
        if (k < 7) load_params(k+2, Pn);   // params two ahead

        // gemm(k) — independent of the in-flight gather loads
        {
            const __half2* cur = s_h[k & 1];
            float2 f0[4], f1[4];
#pragma unroll
            for (int i = 0; i < 4; ++i){
                f0[i] = __half22float2(cur[(g*4 + i)*67 + p0]);
                f1[i] = __half22float2(cur[(g*4 + i)*67 + p1]);
            }
            float sm0[8] = {f0[0].x,f0[0].y,f0[1].x,f0[1].y,f0[2].x,f0[2].y,f0[3].x,f0[3].y};
            float sm1[8] = {f1[0].x,f1[0].y,f1[1].x,f1[1].y,f1[2].x,f1[2].y,f1[3].x,f1[3].y};
            const ulonglong2* wk = reinterpret_cast<const ulonglong2*>(&s_w[(k*8 + g)*64]);
#pragma unroll
            for (int cig = 0; cig < 8; ++cig){
                ulonglong2 wab = wk[cig*2];
                ulonglong2 wcd = wk[cig*2+1];
                ull vv0 = pk2(sm0[cig], sm0[cig]);
                ull vv1 = pk2(sm1[cig], sm1[cig]);
                acc[0] = fma2(vv0, wab.x, acc[0]);
                acc[1] = fma2(vv0, wab.y, acc[1]);
                acc[2] = fma2(vv0, wcd.x, acc[2]);
                acc[3] = fma2(vv0, wcd.y, acc[3]);
                acc[4] = fma2(vv1, wab.x, acc[4]);
                acc[5] = fma2(vv1, wab.y, acc[5]);
                acc[6] = fma2(vv1, wcd.x, acc[6]);
                acc[7] = fma2(vv1, wcd.y, acc[7]);
            }
        }

        if (k < 8) combine_store(s_h[(k+1) & 1]);
        if (k < 7){ P[0]=Pn[0]; P[1]=Pn[1]; P[2]=Pn[2]; P[3]=Pn[3]; }
    }

    // epilogue: direct coalesced stores (lane = pixel -> consecutive x)
    float* orow = out + ((size_t)b*64*128 + y)*128 + x0;
#pragma unroll
    for (int op = 0; op < 4; ++op){
        int o0 = g*8 + 2*op;
        float b0 = __ldg(&db[o0]), b1 = __ldg(&db[o0+1]);
        float lo, hi;
        unpk2(acc[op], lo, hi);
        orow[(size_t)o0*16384 + p0]     = lo + b0;
        orow[(size_t)(o0+1)*16384 + p0] = hi + b1;
        unpk2(acc[4+op], lo, hi);
        orow[(size_t)o0*16384 + p1]     = lo + b0;
        orow[(size_t)(o0+1)*16384 + p1] = hi + b1;
    }
}

extern "C" void kernel_launch(void* const* d_in, const int* in_sizes, int n_in,
                              void* d_out, int out_size)
{
    const float* x  = (const float*)d_in[0];
    const float* ow = (const float*)d_in[1];
    const float* ob = (const float*)d_in[2];
    const float* pa = (const float*)d_in[3];
    const float* dw = (const float*)d_in[4];
    const float* db = (const float*)d_in[5];
    float* out = (float*)d_out;

    k_offset<<<dim3(4, 16, 8), 128>>>(x, ow, ob, pa, dw);
    k_deform<<<dim3(2, 128, 8), 256>>>(db, out);
}

// round 17
// speedup vs baseline: 1.0857x; 1.0830x over previous
#include <cuda_runtime.h>
#include <cuda_fp16.h>
#include <cstdint>

typedef unsigned long long ull;

__device__ __half g_xh[8*128*128*64];   // NHWC fp16 copy of x
__device__ uint4  g_bwi[8*128*9*128];   // {hw00|01, hw10|11, lin00|lin11<<16, 0}
__device__ float  g_w[4608];            // deform weights [k][g][cig][o8]

static __device__ __forceinline__ ull pk2(float lo, float hi){
    ull r; asm("mov.b64 %0, {%1, %2};" : "=l"(r) : "f"(lo), "f"(hi)); return r;
}
static __device__ __forceinline__ void unpk2(ull v, float& lo, float& hi){
    asm("mov.b64 {%0, %1}, %2;" : "=f"(lo), "=f"(hi) : "l"(v));
}
static __device__ __forceinline__ ull fma2(ull a, ull b, ull c){
    ull d; asm("fma.rn.f32x2 %0, %1, %2, %3;" : "=l"(d) : "l"(a), "l"(b), "l"(c)); return d;
}

// ---------------------------------------------------------------
// Kernel 1: offset conv 64->18 + bias + PReLU -> packed bilinear
// params (g_bwi), plus fp16 NHWC emit of x, plus (block 0) deform-
// weight transpose. 128 thr = 32x8 px tile, 2 px/thread, chunked
// channels, register prefetch, 1 bar/chunk. (Frozen core.)
// ---------------------------------------------------------------
__global__ __launch_bounds__(128) void k_offset(const float* __restrict__ x,
                                                const float* __restrict__ ow,
                                                const float* __restrict__ ob,
                                                const float* __restrict__ pa,
                                                const float* __restrict__ dw)
{
    __shared__ float tile[2][2720];            // [c(8)][r(10)][col(34)]
    __shared__ __align__(16) ull wch[2][720];  // [(c*9+k)][10 ull rows]

    int tid = threadIdx.x;
    int ty = tid >> 4, txq = (tid & 15) * 2;
    int x0 = blockIdx.x*32, y0 = blockIdx.y*8, b = blockIdx.z;

    if (blockIdx.x == 0 && blockIdx.y == 0 && blockIdx.z == 0){
        for (int i = tid; i < 4608; i += 128){
            float v = __ldg(&dw[i]);
            int o = i / 72, r = i - o*72;
            int cig = r / 9, k = r - cig*9;
            g_w[((k*8 + (o>>3))*8 + cig)*8 + (o&7)] = v;
        }
    }

    int t_off[22]; unsigned tmask = 0;
#pragma unroll
    for (int s = 0; s < 22; ++s){
        int i = tid + s*128;
        int c = i / 340, rr = i - c*340;
        int r = rr / 34, col = rr - r*34;
        int gy = y0 - 1 + r, gx = x0 - 1 + col;
        t_off[s] = c*16384 + gy*128 + gx;
        if (i < 2720 && (unsigned)gy < 128u && (unsigned)gx < 128u) tmask |= (1u << s);
    }
    int w_src[11], w_dst[11];
#pragma unroll
    for (int s = 0; s < 11; ++s){
        int i = tid + s*128;
        int oc = i / 72, r = i - oc*72;
        w_src[s] = (i < 1296) ? (oc*576 + r) : -1;
        w_dst[s] = r*20 + oc;
    }
    const float* xb = x + (size_t)b*(64*16384);

    ull acc0[9], acc1[9];
#pragma unroll
    for (int o9 = 0; o9 < 9; ++o9){
        ull b2 = pk2(__ldg(&ob[2*o9]), __ldg(&ob[2*o9+1]));
        acc0[o9] = b2; acc1[o9] = b2;
    }

#pragma unroll
    for (int s = 0; s < 11; ++s)
        if (w_src[s] >= 0)
            reinterpret_cast<float*>(wch[0])[w_dst[s]] = __ldg(&ow[w_src[s]]);
#pragma unroll
    for (int s = 0; s < 22; ++s){
        int i = tid + s*128;
        if (i < 2720)
            tile[0][i] = (tmask >> s & 1u) ? __ldg(&xb[t_off[s]]) : 0.f;
    }

    for (int ch = 0; ch < 8; ++ch){
        __syncthreads();
        int bf = ch & 1;
        float wv[11], tv[22];
        if (ch < 7){
            int c0n = (ch+1)*8;
#pragma unroll
            for (int s = 0; s < 11; ++s)
                wv[s] = (w_src[s] >= 0) ? __ldg(&ow[w_src[s] + c0n*9]) : 0.f;
#pragma unroll
            for (int s = 0; s < 22; ++s)
                tv[s] = (tmask >> s & 1u) ? __ldg(&xb[t_off[s] + c0n*16384]) : 0.f;
        }

        int c0 = ch*8;
#pragma unroll
        for (int e = 0; e < 2; ++e){
            int base = (ty+1)*34 + (txq+1+e);
            __half2 h[4];
            h[0] = __floats2half2_rn(tile[bf][0*340+base], tile[bf][1*340+base]);
            h[1] = __floats2half2_rn(tile[bf][2*340+base], tile[bf][3*340+base]);
            h[2] = __floats2half2_rn(tile[bf][4*340+base], tile[bf][5*340+base]);
            h[3] = __floats2half2_rn(tile[bf][6*340+base], tile[bf][7*340+base]);
            *reinterpret_cast<uint4*>(
                g_xh + ((size_t)(b*128 + y0+ty)*128 + x0+txq+e)*64 + c0)
                = *reinterpret_cast<const uint4*>(h);
        }

        for (int c = 0; c < 8; ++c){
#pragma unroll
            for (int ky = 0; ky < 3; ++ky){
                int rbase = c*340 + (ty+ky)*34 + txq;
                float2 va = *reinterpret_cast<const float2*>(&tile[bf][rbase]);
                float2 vb = *reinterpret_cast<const float2*>(&tile[bf][rbase+2]);
                float v[4] = {va.x, va.y, vb.x, vb.y};
#pragma unroll
                for (int kx = 0; kx < 3; ++kx){
                    const ulonglong2* wp2 = reinterpret_cast<const ulonglong2*>(
                        &wch[bf][(c*9 + ky*3 + kx)*10]);
                    ulonglong2 w01 = wp2[0], w23 = wp2[1], w45 = wp2[2], w67 = wp2[3];
                    ull w8 = wch[bf][(c*9 + ky*3 + kx)*10 + 8];
                    ull vv0 = pk2(v[kx],   v[kx]);
                    ull vv1 = pk2(v[kx+1], v[kx+1]);
                    acc0[0] = fma2(vv0, w01.x, acc0[0]); acc1[0] = fma2(vv1, w01.x, acc1[0]);
                    acc0[1] = fma2(vv0, w01.y, acc0[1]); acc1[1] = fma2(vv1, w01.y, acc1[1]);
                    acc0[2] = fma2(vv0, w23.x, acc0[2]); acc1[2] = fma2(vv1, w23.x, acc1[2]);
                    acc0[3] = fma2(vv0, w23.y, acc0[3]); acc1[3] = fma2(vv1, w23.y, acc1[3]);
                    acc0[4] = fma2(vv0, w45.x, acc0[4]); acc1[4] = fma2(vv1, w45.x, acc1[4]);
                    acc0[5] = fma2(vv0, w45.y, acc0[5]); acc1[5] = fma2(vv1, w45.y, acc1[5]);
                    acc0[6] = fma2(vv0, w67.x, acc0[6]); acc1[6] = fma2(vv1, w67.x, acc1[6]);
                    acc0[7] = fma2(vv0, w67.y, acc0[7]); acc1[7] = fma2(vv1, w67.y, acc1[7]);
                    acc0[8] = fma2(vv0, w8,    acc0[8]); acc1[8] = fma2(vv1, w8,    acc1[8]);
                }
            }
        }

        if (ch < 7){
            int nb = bf ^ 1;
#pragma unroll
            for (int s = 0; s < 11; ++s)
                if (w_src[s] >= 0)
                    reinterpret_cast<float*>(wch[nb])[w_dst[s]] = wv[s];
#pragma unroll
            for (int s = 0; s < 22; ++s){
                int i = tid + s*128;
                if (i < 2720) tile[nb][i] = tv[s];
            }
        }
    }

    // epilogue: PReLU + packed bilinear params (one STG.128 per px-tap)
    float a = __ldg(&pa[0]);
    int yy = y0 + ty;
#pragma unroll
    for (int e = 0; e < 2; ++e){
        int xx = x0 + txq + e;
#pragma unroll
        for (int k = 0; k < 9; ++k){
            float dy, dx;
            unpk2(e ? acc1[k] : acc0[k], dy, dx);
            dy = dy > 0.f ? dy : a*dy;
            dx = dx > 0.f ? dx : a*dx;
            float py  = (float)yy + (float)(k/3 - 1) + dy;
            float pxx = (float)xx + (float)(k%3 - 1) + dx;
            float y0f = floorf(py), x0f = floorf(pxx);
            float fy = py - y0f, fx = pxx - x0f;
            float vy0 = (y0f >=  0.f && y0f <= 127.f) ? 1.f : 0.f;
            float vy1 = (y0f >= -1.f && y0f <= 126.f) ? 1.f : 0.f;
            float vx0 = (x0f >=  0.f && x0f <= 127.f) ? 1.f : 0.f;
            float vx1 = (x0f >= -1.f && x0f <= 126.f) ? 1.f : 0.f;
            float w00 = (1.f-fy)*(1.f-fx)*vy0*vx0;
            float w01 = (1.f-fy)*fx*vy0*vx1;
            float w10 = fy*(1.f-fx)*vy1*vx0;
            float w11 = fy*fx*vy1*vx1;
            __half2 hxy = __floats2half2_rn(w00, w01);
            __half2 hzw = __floats2half2_rn(w10, w11);
            int y0i = (int)y0f, x0i = (int)x0f;
            int yc0 = min(max(y0i,   0), 127), yc1 = min(max(y0i+1, 0), 127);
            int xc0 = min(max(x0i,   0), 127), xc1 = min(max(x0i+1, 0), 127);
            unsigned lin00 = (unsigned)(yc0*128 + xc0);
            unsigned lin11 = (unsigned)(yc1*128 + xc1);
            uint4 o;
            o.x = *reinterpret_cast<unsigned*>(&hxy);
            o.y = *reinterpret_cast<unsigned*>(&hzw);
            o.z = lin00 | (lin11 << 16);
            o.w = 0u;
            g_bwi[((size_t)(b*128 + yy)*9 + k)*128 + xx] = o;
        }
    }
}

// ---------------------------------------------------------------
// Kernel 2: deformable grouped conv (R13 structure restored).
// Block 256 thr = 64 px of a row. fp16 corner gathers + HFMA2
// bilinear combine; params via single LDG.128 (packed g_bwi);
// half2 sample smem [c2][p] pitch 67 (conflict-free) double-
// buffered + smem weights, 1 bar/k. Gemm in fp32 f32x2.
// ---------------------------------------------------------------
__global__ __launch_bounds__(256) void k_deform(const float* __restrict__ db,
                                                float* __restrict__ out)
{
    __shared__ __align__(16) float s_w[4608];        // [k][g][cig][o8]
    __shared__ __align__(16) __half2 s_h[2][32*67];  // [c2][p] pitch 67

    int tid = threadIdx.x;
    int lane = tid & 31, wid = tid >> 5;
    int b = blockIdx.z, y = blockIdx.y, x0 = blockIdx.x*64;

    {
        const uint4* src = reinterpret_cast<const uint4*>(g_w);
        uint4* dst = reinterpret_cast<uint4*>(s_w);
        for (int i = tid; i < 1152; i += 256) dst[i] = src[i];
    }

    int q = lane & 15, ph = lane >> 4;    // phase-A identity
    int g = wid;                          // phase-B identity
    int p0 = lane, p1 = lane + 32;

    const uint2* xh = reinterpret_cast<const uint2*>(g_xh) + (size_t)b*(128*128*16);
    size_t rowp = ((size_t)(b*128 + y))*9;

    ull acc[8] = {0,0,0,0,0,0,0,0};       // [px(2)][opair(4)]

    auto gather = [&](int kk, __half2* buf){
#pragma unroll
        for (int j = 0; j < 4; ++j){
            int pp = wid*8 + j*2 + ph;
            uint4 P = __ldg(&g_bwi[(rowp + kk)*128 + x0 + pp]);
            __half2 wxy = *reinterpret_cast<__half2*>(&P.x);
            __half2 wzw = *reinterpret_cast<__half2*>(&P.y);
            __half2 h00 = __low2half2(wxy), h01 = __high2half2(wxy);
            __half2 h10 = __low2half2(wzw), h11 = __high2half2(wzw);
            unsigned bi = P.z;
            int lin00 = bi & 0xFFFFu, lin11 = bi >> 16;
            int xc0 = lin00 & 127, xc1 = lin11 & 127;
            int y0b = lin00 - xc0, y1b = lin11 - xc1;
            uint2 u00 = __ldg(&xh[(y0b + xc0)*16 + q]);
            uint2 u01 = __ldg(&xh[(y0b + xc1)*16 + q]);
            uint2 u10 = __ldg(&xh[(y1b + xc0)*16 + q]);
            uint2 u11 = __ldg(&xh[(y1b + xc1)*16 + q]);
            __half2 sa = __hmul2(h00, *reinterpret_cast<__half2*>(&u00.x));
            sa = __hfma2(h01, *reinterpret_cast<__half2*>(&u01.x), sa);
            sa = __hfma2(h10, *reinterpret_cast<__half2*>(&u10.x), sa);
            sa = __hfma2(h11, *reinterpret_cast<__half2*>(&u11.x), sa);
            __half2 sb = __hmul2(h00, *reinterpret_cast<__half2*>(&u00.y));
            sb = __hfma2(h01, *reinterpret_cast<__half2*>(&u01.y), sb);
            sb = __hfma2(h10, *reinterpret_cast<__half2*>(&u10.y), sb);
            sb = __hfma2(h11, *reinterpret_cast<__half2*>(&u11.y), sb);
            buf[(2*q+0)*67 + pp] = sa;
            buf[(2*q+1)*67 + pp] = sb;
        }
    };

    gather(0, s_h[0]);

#pragma unroll 1
    for (int k = 0; k < 9; ++k){
        __syncthreads();      // weights + buf[k&1] ready; prior gemm reads done
        const __half2* cur = s_h[k & 1];
        {
            float2 f0[4], f1[4];
#pragma unroll
            for (int i = 0; i < 4; ++i){
                f0[i] = __half22float2(cur[(g*4 + i)*67 + p0]);
                f1[i] = __half22float2(cur[(g*4 + i)*67 + p1]);
            }
            float sm0[8] = {f0[0].x,f0[0].y,f0[1].x,f0[1].y,f0[2].x,f0[2].y,f0[3].x,f0[3].y};
            float sm1[8] = {f1[0].x,f1[0].y,f1[1].x,f1[1].y,f1[2].x,f1[2].y,f1[3].x,f1[3].y};
            const ulonglong2* wk = reinterpret_cast<const ulonglong2*>(&s_w[(k*8 + g)*64]);
#pragma unroll
            for (int cig = 0; cig < 8; ++cig){
                ulonglong2 wab = wk[cig*2];
                ulonglong2 wcd = wk[cig*2+1];
                ull vv0 = pk2(sm0[cig], sm0[cig]);
                ull vv1 = pk2(sm1[cig], sm1[cig]);
                acc[0] = fma2(vv0, wab.x, acc[0]);
                acc[1] = fma2(vv0, wab.y, acc[1]);
                acc[2] = fma2(vv0, wcd.x, acc[2]);
                acc[3] = fma2(vv0, wcd.y, acc[3]);
                acc[4] = fma2(vv1, wab.x, acc[4]);
                acc[5] = fma2(vv1, wab.y, acc[5]);
                acc[6] = fma2(vv1, wcd.x, acc[6]);
                acc[7] = fma2(vv1, wcd.y, acc[7]);
            }
        }
        if (k < 8) gather(k+1, s_h[(k+1) & 1]);
    }

    // epilogue: direct coalesced stores (lane = pixel -> consecutive x)
    float* orow = out + ((size_t)b*64*128 + y)*128 + x0;
#pragma unroll
    for (int op = 0; op < 4; ++op){
        int o0 = g*8 + 2*op;
        float b0 = __ldg(&db[o0]), b1 = __ldg(&db[o0+1]);
        float lo, hi;
        unpk2(acc[op], lo, hi);
        orow[(size_t)o0*16384 + p0]     = lo + b0;
        orow[(size_t)(o0+1)*16384 + p0] = hi + b1;
        unpk2(acc[4+op], lo, hi);
        orow[(size_t)o0*16384 + p1]     = lo + b0;
        orow[(size_t)(o0+1)*16384 + p1] = hi + b1;
    }
}

extern "C" void kernel_launch(void* const* d_in, const int* in_sizes, int n_in,
                              void* d_out, int out_size)
{
    const float* x  = (const float*)d_in[0];
    const float* ow = (const float*)d_in[1];
    const float* ob = (const float*)d_in[2];
    const float* pa = (const float*)d_in[3];
    const float* dw = (const float*)d_in[4];
    const float* db = (const float*)d_in[5];
    float* out = (float*)d_out;

    k_offset<<<dim3(4, 16, 8), 128>>>(x, ow, ob, pa, dw);
    k_deform<<<dim3(2, 128, 8), 256>>>(db, out);
}